// round 1
// baseline (speedup 1.0000x reference)
#include <cuda_runtime.h>
#include <math.h>
#include <stdint.h>

#define NTOK 8192
#define DIM  1024
#define VD   32
#define KCB  4096

// ---------------- device scratch (no allocations allowed) ----------------
__device__ float g_embn[KCB * VD];   // normalized codebook [k][v]
__device__ float g_hp[NTOK * VD];    // normalized projected tokens [t][v]
__device__ float g_hvq[NTOK * VD];   // soft-quantized tokens [t][v]
__device__ int   g_code[NTOK];

// ---------------- warp reduce helpers ----------------
__device__ __forceinline__ float warpSum(float v) {
#pragma unroll
    for (int o = 16; o; o >>= 1) v += __shfl_xor_sync(0xffffffffu, v, o);
    return v;
}
__device__ __forceinline__ float warpMax(float v) {
#pragma unroll
    for (int o = 16; o; o >>= 1) v = fmaxf(v, __shfl_xor_sync(0xffffffffu, v, o));
    return v;
}

// ---------------- Kernel A: normalize codebook rows ----------------
// grid 512 x block 256: one warp per codebook row (4096 rows)
__global__ void k_embnorm(const float* __restrict__ emb) {
    int row  = blockIdx.x * 8 + (threadIdx.x >> 5);
    int lane = threadIdx.x & 31;
    float x  = emb[row * VD + lane];
    float ss = warpSum(x * x);
    g_embn[row * VD + lane] = x * rsqrtf(ss);
}

// ---------------- Kernel B: hp = normalize(h @ Wp^T + bp) ----------------
// grid 256 x block 256 (8 warps). Block handles 32 tokens.
// lane = token, warp owns 4 output dims v. D tiled in chunks of 128 through smem.
__global__ void k_proj(const float* __restrict__ h,
                       const float* __restrict__ Wp,
                       const float* __restrict__ bp) {
    __shared__ __align__(16) float wp_s[32][128];  // [v][d'] broadcast reads
    __shared__ __align__(16) float h_s[32][132];   // [t][d'] lane-varying float4 reads (132/4=33 odd -> conflict free)
    __shared__ __align__(16) float hpbuf[32][33];

    int tid = threadIdx.x, warp = tid >> 5, lane = tid & 31;
    int t0 = blockIdx.x * 32;
    int v0 = warp * 4;
    float acc0 = 0.f, acc1 = 0.f, acc2 = 0.f, acc3 = 0.f;

    for (int c = 0; c < 8; c++) {
        __syncthreads();
#pragma unroll
        for (int i = tid; i < 4096; i += 256) {
            int v = i >> 7, d = i & 127;
            wp_s[v][d] = Wp[v * DIM + c * 128 + d];
        }
#pragma unroll
        for (int i = tid; i < 4096; i += 256) {
            int t = i >> 7, d = i & 127;
            h_s[t][d] = h[(size_t)(t0 + t) * DIM + c * 128 + d];
        }
        __syncthreads();
#pragma unroll 4
        for (int dq = 0; dq < 128; dq += 4) {
            float4 hv = *(const float4*)&h_s[lane][dq];
            float4 w0 = *(const float4*)&wp_s[v0 + 0][dq];
            float4 w1 = *(const float4*)&wp_s[v0 + 1][dq];
            float4 w2 = *(const float4*)&wp_s[v0 + 2][dq];
            float4 w3 = *(const float4*)&wp_s[v0 + 3][dq];
            acc0 += hv.x * w0.x + hv.y * w0.y + hv.z * w0.z + hv.w * w0.w;
            acc1 += hv.x * w1.x + hv.y * w1.y + hv.z * w1.z + hv.w * w1.w;
            acc2 += hv.x * w2.x + hv.y * w2.y + hv.z * w2.z + hv.w * w2.w;
            acc3 += hv.x * w3.x + hv.y * w3.y + hv.z * w3.z + hv.w * w3.w;
        }
    }
    __syncthreads();
    hpbuf[lane][v0 + 0] = acc0 + bp[v0 + 0];
    hpbuf[lane][v0 + 1] = acc1 + bp[v0 + 1];
    hpbuf[lane][v0 + 2] = acc2 + bp[v0 + 2];
    hpbuf[lane][v0 + 3] = acc3 + bp[v0 + 3];
    __syncthreads();
    // normalize: warp handles 4 tokens, lane = v
#pragma unroll
    for (int q = 0; q < 4; q++) {
        int t = warp * 4 + q;
        float x = hpbuf[t][lane];
        float ss = warpSum(x * x);
        g_hp[(size_t)(t0 + t) * VD + lane] = x * rsqrtf(ss);
    }
}

// ---------------- Kernel C: VQ core (scores + online softmax + weighted sum + argmax) --
// grid 512 x block 128 (4 warps). Block handles 16 tokens, each warp 4 tokens.
// K tiled in chunks of 64 codes.
__global__ void k_vq(const float* __restrict__ attn_mask) {
    __shared__ __align__(16) float e_s[64][36];  // [k'][v]: score pass; lane=k' rows (36/4=9 odd, conflict free f4)
    __shared__ __align__(16) float e_t[32][68];  // [v][k']: accum pass; lane=v rows (68/4=17 odd, conflict free f4)
    __shared__ __align__(16) float p_s[16][68];  // probs [t_local][k'], broadcast f4 reads
    __shared__ __align__(16) float hp_s[16][36]; // [t_local][v], broadcast f4 reads

    int tid = threadIdx.x, warp = tid >> 5, lane = tid & 31;
    int t0 = blockIdx.x * 16;
    int tl = warp * 4;  // this warp's local token base

    for (int i = tid; i < 16 * 32; i += 128) {
        int t = i >> 5, v = i & 31;
        hp_s[t][v] = g_hp[(size_t)(t0 + t) * VD + v];
    }

    float m[4]  = {-INFINITY, -INFINITY, -INFINITY, -INFINITY};
    float Z[4]  = {0.f, 0.f, 0.f, 0.f};
    float y[4]  = {0.f, 0.f, 0.f, 0.f};   // lane = v component
    float bv[4] = {-INFINITY, -INFINITY, -INFINITY, -INFINITY};
    int   bk[4] = {0, 0, 0, 0};

    for (int c = 0; c < 64; c++) {
        __syncthreads();
        for (int i = tid; i < 2048; i += 128) {
            int k = i >> 5, v = i & 31;
            float e = g_embn[(size_t)(c * 64 + k) * VD + v];
            e_s[k][v] = e;
            e_t[v][k] = e;
        }
        __syncthreads();

        // ---- score pass: lane owns codes k' = lane and lane+32 ----
        float s0[4] = {0.f, 0.f, 0.f, 0.f};
        float s1[4] = {0.f, 0.f, 0.f, 0.f};
#pragma unroll
        for (int vq = 0; vq < 32; vq += 4) {
            float4 e0 = *(const float4*)&e_s[lane][vq];
            float4 e1 = *(const float4*)&e_s[lane + 32][vq];
#pragma unroll
            for (int q = 0; q < 4; q++) {
                float4 hq = *(const float4*)&hp_s[tl + q][vq];
                s0[q] += hq.x * e0.x + hq.y * e0.y + hq.z * e0.z + hq.w * e0.w;
                s1[q] += hq.x * e1.x + hq.y * e1.y + hq.z * e1.z + hq.w * e1.w;
            }
        }

        // ---- online softmax update + probs to smem ----
        float corr[4];
#pragma unroll
        for (int q = 0; q < 4; q++) {
            float l0 = 2.0f * s0[q], l1 = 2.0f * s1[q];
            int k0 = c * 64 + lane, k1 = k0 + 32;
            if (l0 > bv[q]) { bv[q] = l0; bk[q] = k0; }
            if (l1 > bv[q]) { bv[q] = l1; bk[q] = k1; }
            float mc = warpMax(fmaxf(l0, l1));
            float nm = fmaxf(m[q], mc);
            corr[q] = __expf(m[q] - nm);     // exp(-inf)=0 on first chunk
            float p0 = __expf(l0 - nm);
            float p1 = __expf(l1 - nm);
            p_s[tl + q][lane]      = p0;
            p_s[tl + q][lane + 32] = p1;
            Z[q] = Z[q] * corr[q] + warpSum(p0 + p1);
            m[q] = nm;
        }

        // ---- accumulate pass: lane = v (same warp wrote p_s, no sync needed) ----
#pragma unroll
        for (int q = 0; q < 4; q++) y[q] *= corr[q];
#pragma unroll
        for (int kq = 0; kq < 64; kq += 4) {
            float4 e4 = *(const float4*)&e_t[lane][kq];
#pragma unroll
            for (int q = 0; q < 4; q++) {
                float4 p4 = *(const float4*)&p_s[tl + q][kq];
                y[q] += e4.x * p4.x + e4.y * p4.y + e4.z * p4.z + e4.w * p4.w;
            }
        }
    }

    // ---- finalize: normalize by Z, mask, argmax reduce ----
#pragma unroll
    for (int q = 0; q < 4; q++) {
        int tok = t0 + tl + q;
        float mk = attn_mask[tok];
        float val = y[q] / Z[q];
        if (mk != 1.0f) val = 0.0f;
        g_hvq[(size_t)tok * VD + lane] = val;

        float b = bv[q];
        int kk = bk[q];
#pragma unroll
        for (int o = 16; o; o >>= 1) {
            float ob = __shfl_xor_sync(0xffffffffu, b, o);
            int   ok = __shfl_xor_sync(0xffffffffu, kk, o);
            if (ob > b || (ob == b && ok < kk)) { b = ob; kk = ok; }
        }
        if (lane == 0) g_code[tok] = (mk != 1.0f) ? 0 : kk;
    }
}

// ---------------- Kernel D: quantized = g_hvq @ Wpi^T + bpi ----------------
// grid 256 x block 256 (8 warps). Block: 32 tokens; warp: 4 tokens; lane = output dim d.
__global__ void k_out(const float* __restrict__ Wpi,
                      const float* __restrict__ bpi,
                      float* __restrict__ out) {
    __shared__ __align__(16) float wpi_s[128][36];  // [d'][v] lane-varying f4 (36/4=9 odd)
    __shared__ __align__(16) float hvq_s[32][32];   // broadcast f4 reads

    int tid = threadIdx.x, warp = tid >> 5, lane = tid & 31;
    int t0 = blockIdx.x * 32;
    int tl = warp * 4;

    for (int i = tid; i < 1024; i += 256) {
        int t = i >> 5, v = i & 31;
        hvq_s[t][v] = g_hvq[(size_t)(t0 + t) * VD + v];
    }

    for (int c = 0; c < 8; c++) {
        __syncthreads();
        for (int i = tid; i < 4096; i += 256) {
            int d = i >> 5, v = i & 31;
            wpi_s[d][v] = Wpi[(size_t)(c * 128 + d) * VD + v];
        }
        __syncthreads();
#pragma unroll
        for (int sub = 0; sub < 4; sub++) {
            int dd = sub * 32 + lane;
            float bb = bpi[c * 128 + dd];
            float a0 = bb, a1 = bb, a2 = bb, a3 = bb;
#pragma unroll
            for (int vq = 0; vq < 32; vq += 4) {
                float4 w4 = *(const float4*)&wpi_s[dd][vq];
                float4 h0 = *(const float4*)&hvq_s[tl + 0][vq];
                float4 h1 = *(const float4*)&hvq_s[tl + 1][vq];
                float4 h2 = *(const float4*)&hvq_s[tl + 2][vq];
                float4 h3 = *(const float4*)&hvq_s[tl + 3][vq];
                a0 += w4.x * h0.x + w4.y * h0.y + w4.z * h0.z + w4.w * h0.w;
                a1 += w4.x * h1.x + w4.y * h1.y + w4.z * h1.z + w4.w * h1.w;
                a2 += w4.x * h2.x + w4.y * h2.y + w4.z * h2.z + w4.w * h2.w;
                a3 += w4.x * h3.x + w4.y * h3.y + w4.z * h3.z + w4.w * h3.w;
            }
            out[(size_t)(t0 + tl + 0) * DIM + c * 128 + dd] = a0;
            out[(size_t)(t0 + tl + 1) * DIM + c * 128 + dd] = a1;
            out[(size_t)(t0 + tl + 2) * DIM + c * 128 + dd] = a2;
            out[(size_t)(t0 + tl + 3) * DIM + c * 128 + dd] = a3;
        }
    }
}

// ---------------- Kernel E: tail (codes as float + vq_loss=0) ----------------
__global__ void k_tail(float* __restrict__ out, int write_loss) {
    int i = blockIdx.x * blockDim.x + threadIdx.x;
    if (i < NTOK) out[(size_t)NTOK * DIM + i] = (float)g_code[i];
    if (i == 0 && write_loss) out[(size_t)NTOK * DIM + NTOK] = 0.0f;
}

// ---------------- launch ----------------
extern "C" void kernel_launch(void* const* d_in, const int* in_sizes, int n_in,
                              void* d_out, int out_size) {
    const float* h    = (const float*)d_in[0];
    const float* mask = (const float*)d_in[1];
    const float* Wp   = (const float*)d_in[2];
    const float* bp   = (const float*)d_in[3];
    const float* Wpi  = (const float*)d_in[4];
    const float* bpi  = (const float*)d_in[5];
    const float* emb  = (const float*)d_in[6];
    float* out = (float*)d_out;

    k_embnorm<<<512, 256>>>(emb);
    k_proj<<<256, 256>>>(h, Wp, bp);
    k_vq<<<512, 128>>>(mask);
    k_out<<<256, 256>>>(Wpi, bpi, out);

    long long need = (long long)NTOK * DIM;
    if ((long long)out_size >= need + NTOK) {
        int wl = ((long long)out_size >= need + NTOK + 1) ? 1 : 0;
        k_tail<<<(NTOK + 255) / 256, 256>>>(out, wl);
    }
}